// round 15
// baseline (speedup 1.0000x reference)
#include <cuda_runtime.h>
#include <cuda_bf16.h>
#include <cuda_fp16.h>
#include <math.h>
#include <stdint.h>

// Problem constants (match reference)
#define NN      50000
#define EE      600000
#define D_IN    128
#define D_H     128
#define D_OUT   64
#define NLAYERS 3
#define NG      64
#define SLOPE   0.2f

// ---------------------------------------------------------------------------
// Device scratch (g_deg/g_total statically zeroed; re-zeroed by k_poolfinal)
// ---------------------------------------------------------------------------
__device__ __align__(16) float  g_h  [NN * D_H];   // fp32 features (residual/pool)
__device__ __align__(16) __half g_hpf[NN * D_H];   // fp16 h@W (aggregation gathers)
__device__ float g_es[NN];
__device__ float g_ed[NN];
__device__ int   g_deg[NN];
__device__ int   g_start[NN];
__device__ int   g_cur[NN];
__device__ int   g_total;
__device__ int   g_csrc[EE];                       // compact CSR-by-dst source ids

__device__ __forceinline__ float leaky(float x) {
    return x >= 0.f ? x : SLOPE * x;
}

__device__ __forceinline__ int load_idx2(const void* p, long long i, int is64) {
    return is64 ? (int)((const long long*)p)[i] : ((const int*)p)[i];
}

// Per-block index-dtype probe (warp ballot into shared flag)
__device__ __forceinline__ void probe_is64(const void* ei, int* flag) {
    if (threadIdx.x < 32) {
        const int* w = (const int*)ei;
        int lane = threadIdx.x;
        int nz = (w[2 * lane + 1] != 0) | (w[2 * (lane + 32) + 1] != 0);
        unsigned bal = __ballot_sync(0xffffffffu, nz);
        if (lane == 0) *flag = (bal == 0u);
    }
}

// pack two floats as f16x2 (one cvt instruction)
__device__ __forceinline__ uint32_t pack_f16(float a, float b) {
    half2 h = __floats2half2_rn(a, b);
    return *(uint32_t*)&h;
}

// m16n8k16 fp16 MMA, fp32 accumulate
__device__ __forceinline__ void mma_f16(float c[4], const uint32_t a[4],
                                        uint32_t b0, uint32_t b1) {
    asm volatile(
        "mma.sync.aligned.m16n8k16.row.col.f32.f16.f16.f32 "
        "{%0,%1,%2,%3}, {%4,%5,%6,%7}, {%8,%9}, {%0,%1,%2,%3};\n"
        : "+f"(c[0]), "+f"(c[1]), "+f"(c[2]), "+f"(c[3])
        : "r"(a[0]), "r"(a[1]), "r"(a[2]), "r"(a[3]), "r"(b0), "r"(b1));
}

__device__ __forceinline__ void ldsm_x4(uint32_t& r0, uint32_t& r1,
                                        uint32_t& r2, uint32_t& r3, uint32_t addr) {
    asm volatile("ldmatrix.sync.aligned.m8n8.x4.shared.b16 {%0,%1,%2,%3}, [%4];"
                 : "=r"(r0), "=r"(r1), "=r"(r2), "=r"(r3) : "r"(addr));
}

__device__ __forceinline__ void ldsm_x4_t(uint32_t& r0, uint32_t& r1,
                                          uint32_t& r2, uint32_t& r3, uint32_t addr) {
    asm volatile("ldmatrix.sync.aligned.m8n8.x4.trans.shared.b16 {%0,%1,%2,%3}, [%4];"
                 : "=r"(r0), "=r"(r1), "=r"(r2), "=r"(r3) : "r"(addr));
}

// ---------------------------------------------------------------------------
// Compact CSR build: hist -> alloc -> scatter (g_deg pre-zeroed)
// ---------------------------------------------------------------------------
__global__ void k_hist(const void* __restrict__ ei) {
    __shared__ int s64;
    probe_is64(ei, &s64);
    __syncthreads();
    int e = blockIdx.x * blockDim.x + threadIdx.x;
    if (e < EE) {
        int d = load_idx2(ei, (long long)EE + e, s64);
        if ((unsigned)d < NN) atomicAdd(&g_deg[d], 1);
    }
}

__global__ void k_alloc() {
    int i = blockIdx.x * blockDim.x + threadIdx.x;
    if (i < NN) {
        int dg = g_deg[i];
        int st = atomicAdd(&g_total, dg);
        g_start[i] = st;
        g_cur[i]   = st;
    }
}

__global__ void k_scatter(const void* __restrict__ ei) {
    __shared__ int s64;
    probe_is64(ei, &s64);
    __syncthreads();
    int e = blockIdx.x * blockDim.x + threadIdx.x;
    if (e < EE) {
        int s = load_idx2(ei, e, s64);
        int d = load_idx2(ei, (long long)EE + e, s64);
        if ((unsigned)d < NN && (unsigned)s < NN) {
            int pos = atomicAdd(&g_cur[d], 1);
            g_csrc[pos] = s;
        }
    }
}

// ---------------------------------------------------------------------------
// fp16 tensor-core GEMM: C[M,128] = A[M,128] @ B[128,128] (+bias)
// Block 64x128, 256 threads (8 warps, 2x4), warp tile 32x32, BK=16,
// double-buffered staging, LDMATRIX fragment loads:
//   A smem [m][16 halves], 48B row stride  -> ldmatrix.x4      (conflict-free)
//   B smem [k][128 halves], 272B row stride -> ldmatrix.x4.trans (conflict-free)
// 4 LDSM per warp-chunk vs 16 scalar LDS previously.
// ---------------------------------------------------------------------------
#define A_STRIDE 12   // uint32 per A row (48 B)
#define B_STRIDE 68   // uint32 per B row (272 B)

template <bool FUSE_ESED, bool HALF_OUT>
__device__ __forceinline__ void mma_gemm_body(const float* __restrict__ A,
                                              const float* __restrict__ B,
                                              const float* __restrict__ bias,
                                              const float* __restrict__ asrc,
                                              const float* __restrict__ adst,
                                              float* __restrict__ C, int M) {
    __shared__ uint32_t As[2][64][A_STRIDE];   // [buf][m][k halves/2]
    __shared__ uint32_t Bs[2][16][B_STRIDE];   // [buf][k][n halves/2]
    __shared__ float es_s[64], ed_s[64];

    const int tid  = threadIdx.x;
    const int warp = tid >> 5, lane = tid & 31;
    const int wm = warp >> 2, wn = warp & 3;   // 2 x 4 warp grid
    const int gid = lane >> 2, tig = lane & 3;
    const int brow = blockIdx.x * 64;

    if (FUSE_ESED && tid < 64) { es_s[tid] = 0.f; ed_s[tid] = 0.f; }

    const int a_r  = tid & 63;
    const int a_kq = (tid >> 6) * 4;   // k offset within chunk: 0,4,8,12
    const int b_bp = tid >> 5;         // 0..7 -> k rows 2b, 2b+1
    const int b_nu = (tid & 31) * 2;   // uint32 col index (n halves /2)

    float acc[2][4][4];
    #pragma unroll
    for (int mt = 0; mt < 2; mt++)
        #pragma unroll
        for (int nt = 0; nt < 4; nt++)
            #pragma unroll
            for (int c = 0; c < 4; c++) acc[mt][nt][c] = 0.f;

    float4 av, bv0, bv1;   // prefetch registers

    auto load_chunk = [&](int kc) {
        int g0 = brow + a_r;
        av = (g0 < M) ? *(const float4*)&A[(size_t)g0 * 128 + kc + a_kq]
                      : make_float4(0.f, 0.f, 0.f, 0.f);
        const float* B0 = &B[(size_t)(kc + 2 * b_bp) * 128 + (tid & 31) * 4];
        bv0 = *(const float4*)B0;
        bv1 = *(const float4*)(B0 + 128);
    };

    auto store_chunk = [&](int buf) {
        // A: row m = a_r, halves a_kq..a_kq+3 -> u32 cols a_kq/2, +1
        *(uint2*)&As[buf][a_r][a_kq / 2] =
            make_uint2(pack_f16(av.x, av.y), pack_f16(av.z, av.w));
        // B: rows k = 2*b_bp, 2*b_bp+1, n halves 4*(tid&31)..+3
        *(uint2*)&Bs[buf][2 * b_bp][b_nu] =
            make_uint2(pack_f16(bv0.x, bv0.y), pack_f16(bv0.z, bv0.w));
        *(uint2*)&Bs[buf][2 * b_bp + 1][b_nu] =
            make_uint2(pack_f16(bv1.x, bv1.y), pack_f16(bv1.z, bv1.w));
    };

    load_chunk(0);
    store_chunk(0);
    __syncthreads();

    const uint32_t as_base0 = (uint32_t)__cvta_generic_to_shared(&As[0][0][0]);
    const uint32_t as_base1 = (uint32_t)__cvta_generic_to_shared(&As[1][0][0]);
    const uint32_t bs_base0 = (uint32_t)__cvta_generic_to_shared(&Bs[0][0][0]);
    const uint32_t bs_base1 = (uint32_t)__cvta_generic_to_shared(&Bs[1][0][0]);

    #pragma unroll 1
    for (int c = 0; c < 8; c++) {
        const int cur = c & 1;
        if (c < 7) load_chunk((c + 1) * 16);

        {
            const uint32_t a_base = cur ? as_base1 : as_base0;
            const uint32_t b_base = cur ? bs_base1 : bs_base0;

            // A fragments: 2 x ldmatrix.x4 (m16 x k16 each)
            uint32_t a[2][4];
            #pragma unroll
            for (int mt = 0; mt < 2; mt++) {
                int mrow = wm * 32 + mt * 16 + (lane & 15);
                uint32_t addr = a_base + mrow * (A_STRIDE * 4) + (lane >> 4) * 16;
                ldsm_x4(a[mt][0], a[mt][1], a[mt][2], a[mt][3], addr);
            }
            // B fragments: 2 x ldmatrix.x4.trans (k16 x n16 each)
            uint32_t b[2][4];
            #pragma unroll
            for (int nb = 0; nb < 2; nb++) {
                int n0 = wn * 32 + nb * 16;
                uint32_t addr = b_base + (lane & 15) * (B_STRIDE * 4)
                              + (n0 + (lane >> 4) * 8) * 2;
                ldsm_x4_t(b[nb][0], b[nb][1], b[nb][2], b[nb][3], addr);
            }
            #pragma unroll
            for (int nt = 0; nt < 4; nt++) {
                uint32_t bh0 = b[nt >> 1][(nt & 1) * 2];
                uint32_t bh1 = b[nt >> 1][(nt & 1) * 2 + 1];
                #pragma unroll
                for (int mt = 0; mt < 2; mt++)
                    mma_f16(acc[mt][nt], a[mt], bh0, bh1);
            }
        }

        if (c < 7) store_chunk(cur ^ 1);
        __syncthreads();
    }

    float as_v[4][2], ad_v[4][2];
    if (FUSE_ESED) {
        #pragma unroll
        for (int nt = 0; nt < 4; nt++) {
            int c0 = wn * 32 + nt * 8 + 2 * tig;
            as_v[nt][0] = asrc[c0]; as_v[nt][1] = asrc[c0 + 1];
            ad_v[nt][0] = adst[c0]; ad_v[nt][1] = adst[c0 + 1];
        }
    }

    #pragma unroll
    for (int mt = 0; mt < 2; mt++) {
        int r0 = brow + wm * 32 + mt * 16 + gid;
        float pe0 = 0.f, pe1 = 0.f, pd0 = 0.f, pd1 = 0.f;
        #pragma unroll
        for (int nt = 0; nt < 4; nt++) {
            int c0 = wn * 32 + nt * 8 + 2 * tig;
            float b0v = bias ? bias[c0]     : 0.f;
            float b1v = bias ? bias[c0 + 1] : 0.f;
            float v00 = acc[mt][nt][0] + b0v, v01 = acc[mt][nt][1] + b1v;
            float v10 = acc[mt][nt][2] + b0v, v11 = acc[mt][nt][3] + b1v;
            if (HALF_OUT) {
                if (r0 < M)     *(half2*)&g_hpf[(size_t)r0 * 128 + c0]       = __floats2half2_rn(v00, v01);
                if (r0 + 8 < M) *(half2*)&g_hpf[(size_t)(r0 + 8) * 128 + c0] = __floats2half2_rn(v10, v11);
            } else {
                if (r0 < M)     *(float2*)&C[(size_t)r0 * 128 + c0]       = make_float2(v00, v01);
                if (r0 + 8 < M) *(float2*)&C[(size_t)(r0 + 8) * 128 + c0] = make_float2(v10, v11);
            }
            if (FUSE_ESED) {
                pe0 += v00 * as_v[nt][0] + v01 * as_v[nt][1];
                pe1 += v10 * as_v[nt][0] + v11 * as_v[nt][1];
                pd0 += v00 * ad_v[nt][0] + v01 * ad_v[nt][1];
                pd1 += v10 * ad_v[nt][0] + v11 * ad_v[nt][1];
            }
        }
        if (FUSE_ESED) {
            #pragma unroll
            for (int o = 1; o <= 2; o <<= 1) {
                pe0 += __shfl_xor_sync(0xffffffffu, pe0, o);
                pe1 += __shfl_xor_sync(0xffffffffu, pe1, o);
                pd0 += __shfl_xor_sync(0xffffffffu, pd0, o);
                pd1 += __shfl_xor_sync(0xffffffffu, pd1, o);
            }
            if (tig == 0) {
                int lr = wm * 32 + mt * 16 + gid;
                atomicAdd(&es_s[lr], pe0);     atomicAdd(&es_s[lr + 8], pe1);
                atomicAdd(&ed_s[lr], pd0);     atomicAdd(&ed_s[lr + 8], pd1);
            }
        }
    }

    if (FUSE_ESED) {
        __syncthreads();
        if (tid < 64 && brow + tid < M) {
            g_es[brow + tid] = es_s[tid];
            g_ed[brow + tid] = ed_s[tid];
        }
    }
}

// mlp1: g_h = x @ W1 + b1 (fp32 out)
__global__ void __launch_bounds__(256, 4) k_mma_x(const float* __restrict__ A,
                                                  const float* __restrict__ B,
                                                  const float* __restrict__ bias) {
    mma_gemm_body<false, false>(A, B, bias, nullptr, nullptr, g_h, NN);
}

// per-layer: g_hpf = fp16(h @ Wg[l]), fused es/ed
__global__ void __launch_bounds__(256, 4) k_mma_h(const float* __restrict__ B,
                                                  const float* __restrict__ asrc,
                                                  const float* __restrict__ adst) {
    mma_gemm_body<true, true>(g_h, B, nullptr, asrc, adst, nullptr, NN);
}

// ---------------------------------------------------------------------------
// GAT aggregation (warp per destination node, compact CSR) — single pass,
// no max-shift softmax, fp16 gather, x4 batched loads.
// ---------------------------------------------------------------------------
__global__ void k_gat_aggr(const float* __restrict__ bg) {
    int warp = (blockIdx.x * blockDim.x + threadIdx.x) >> 5;
    int lane = threadIdx.x & 31;
    if (warp >= NN) return;
    const int d = warp;
    const int lo = g_start[d], hi = lo + g_deg[d];
    const float ed_d = g_ed[d];
    const float e_self = leaky(g_es[d] + ed_d);

    float ex_self = expf(e_self);
    float z = ex_self;
    uint2 sv = *(const uint2*)&g_hpf[(size_t)d * 128 + 4 * lane];
    float2 s0 = __half22float2(*(half2*)&sv.x);
    float2 s1 = __half22float2(*(half2*)&sv.y);
    float ax = ex_self * s0.x, ay = ex_self * s0.y;
    float az = ex_self * s1.x, aw = ex_self * s1.y;

    const size_t fo = 4 * lane;
    int j = lo;

    for (; j + 4 <= hi; j += 4) {
        int i0 = g_csrc[j],     i1 = g_csrc[j + 1];
        int i2 = g_csrc[j + 2], i3 = g_csrc[j + 3];
        float e0 = g_es[i0], e1 = g_es[i1], e2 = g_es[i2], e3 = g_es[i3];
        uint2 w0 = *(const uint2*)&g_hpf[(size_t)i0 * 128 + fo];
        uint2 w1 = *(const uint2*)&g_hpf[(size_t)i1 * 128 + fo];
        uint2 w2 = *(const uint2*)&g_hpf[(size_t)i2 * 128 + fo];
        uint2 w3 = *(const uint2*)&g_hpf[(size_t)i3 * 128 + fo];

        float x0 = expf(leaky(e0 + ed_d));
        float x1 = expf(leaky(e1 + ed_d));
        float x2 = expf(leaky(e2 + ed_d));
        float x3 = expf(leaky(e3 + ed_d));
        z += (x0 + x1) + (x2 + x3);

        float2 a0 = __half22float2(*(half2*)&w0.x), b0 = __half22float2(*(half2*)&w0.y);
        float2 a1 = __half22float2(*(half2*)&w1.x), b1 = __half22float2(*(half2*)&w1.y);
        float2 a2 = __half22float2(*(half2*)&w2.x), b2 = __half22float2(*(half2*)&w2.y);
        float2 a3 = __half22float2(*(half2*)&w3.x), b3 = __half22float2(*(half2*)&w3.y);

        ax = fmaf(x0, a0.x, ax); ay = fmaf(x0, a0.y, ay);
        az = fmaf(x0, b0.x, az); aw = fmaf(x0, b0.y, aw);
        ax = fmaf(x1, a1.x, ax); ay = fmaf(x1, a1.y, ay);
        az = fmaf(x1, b1.x, az); aw = fmaf(x1, b1.y, aw);
        ax = fmaf(x2, a2.x, ax); ay = fmaf(x2, a2.y, ay);
        az = fmaf(x2, b2.x, az); aw = fmaf(x2, b2.y, aw);
        ax = fmaf(x3, a3.x, ax); ay = fmaf(x3, a3.y, ay);
        az = fmaf(x3, b3.x, az); aw = fmaf(x3, b3.y, aw);
    }

    for (; j < hi; ++j) {
        int s = g_csrc[j];
        float ex = expf(leaky(g_es[s] + ed_d));
        z += ex;
        uint2 wv = *(const uint2*)&g_hpf[(size_t)s * 128 + fo];
        float2 w0 = __half22float2(*(half2*)&wv.x);
        float2 w1 = __half22float2(*(half2*)&wv.y);
        ax = fmaf(ex, w0.x, ax);
        ay = fmaf(ex, w0.y, ay);
        az = fmaf(ex, w1.x, az);
        aw = fmaf(ex, w1.y, aw);
    }
    const float invz = 1.0f / z;

    float4* h4 = (float4*)g_h;
    float4 b = ((const float4*)bg)[lane];
    float4 hin = h4[(size_t)d * 32 + lane];
    float4 o;
    o.x = fmaxf(fmaf(ax, invz, b.x), 0.f) + hin.x;
    o.y = fmaxf(fmaf(ay, invz, b.y), 0.f) + hin.y;
    o.z = fmaxf(fmaf(az, invz, b.z), 0.f) + hin.z;
    o.w = fmaxf(fmaf(aw, invz, b.w), 0.f) + hin.w;
    h4[(size_t)d * 32 + lane] = o;
}

// ---------------------------------------------------------------------------
// Fused pool + final projection; re-zeroes g_deg/g_total for the next run.
// ---------------------------------------------------------------------------
__global__ void k_poolfinal(const void* __restrict__ ei,
                            const void* __restrict__ batch,
                            const float* __restrict__ W2,
                            const float* __restrict__ b2,
                            float* __restrict__ out) {
    __shared__ float ps[128];
    __shared__ int s_lo, s_hi, s64;
    const int g = blockIdx.x;
    const int tid = threadIdx.x;
    probe_is64(ei, &s64);
    __syncthreads();
    if (tid == 0) {
        int lo = 0, hi = NN;
        while (lo < hi) { int mid = (lo + hi) >> 1; if (load_idx2(batch, mid, s64) < g) lo = mid + 1; else hi = mid; }
        s_lo = lo;
        lo = 0; hi = NN;
        int g1 = g + 1;
        while (lo < hi) { int mid = (lo + hi) >> 1; if (load_idx2(batch, mid, s64) < g1) lo = mid + 1; else hi = mid; }
        s_hi = lo;
    }
    __syncthreads();
    float acc = 0.f;
    for (int i = s_lo; i < s_hi; ++i) acc += g_h[(size_t)i * 128 + tid];
    ps[tid] = acc;
    __syncthreads();
    if (tid < 64) {
        float o = b2[tid];
        #pragma unroll 8
        for (int k = 0; k < 128; ++k)
            o = fmaf(ps[k], W2[k * 64 + tid], o);
        out[g * 64 + tid] = o;
    }
    // reset CSR counters for the next invocation
    for (int i = g * 128 + tid; i < NN; i += NG * 128) g_deg[i] = 0;
    if (g == 0 && tid == 0) g_total = 0;
}

// ---------------------------------------------------------------------------
// Launch (11 kernels)
// ---------------------------------------------------------------------------
extern "C" void kernel_launch(void* const* d_in, const int* in_sizes, int n_in,
                              void* d_out, int out_size) {
    const float* x     = (const float*)d_in[0];
    const void*  ei    = d_in[1];
    const void*  batch = d_in[2];
    const float* W1    = (const float*)d_in[3];
    const float* b1    = (const float*)d_in[4];
    const float* Wg    = (const float*)d_in[5];
    const float* asrc  = (const float*)d_in[6];
    const float* adst  = (const float*)d_in[7];
    const float* bg    = (const float*)d_in[8];
    const float* W2    = (const float*)d_in[9];
    const float* b2    = (const float*)d_in[10];
    float*       out   = (float*)d_out;

    k_hist<<<(EE + 255) / 256, 256>>>(ei);
    k_alloc<<<(NN + 255) / 256, 256>>>();
    k_scatter<<<(EE + 255) / 256, 256>>>(ei);

    const int gemm_blocks = (NN + 63) / 64;
    const int node_warp_blocks = (NN * 32 + 255) / 256;

    k_mma_x<<<gemm_blocks, 256>>>(x, W1, b1);

    for (int l = 0; l < NLAYERS; ++l) {
        k_mma_h<<<gemm_blocks, 256>>>(Wg + (size_t)l * 128 * 128,
                                      asrc + l * 128, adst + l * 128);
        k_gat_aggr<<<node_warp_blocks, 256>>>(bg + l * 128);
    }

    k_poolfinal<<<NG, 128>>>(ei, batch, W2, b2, out);
}

// round 16
// speedup vs baseline: 1.0349x; 1.0349x over previous
#include <cuda_runtime.h>
#include <cuda_bf16.h>
#include <cuda_fp16.h>
#include <math.h>
#include <stdint.h>

// Problem constants (match reference)
#define NN      50000
#define EE      600000
#define D_IN    128
#define D_H     128
#define D_OUT   64
#define NLAYERS 3
#define NG      64
#define SLOPE   0.2f

// ---------------------------------------------------------------------------
// Device scratch (g_deg/g_total statically zeroed; re-zeroed by k_poolfinal)
// ---------------------------------------------------------------------------
__device__ __align__(16) float  g_h  [NN * D_H];   // fp32 features (residual/pool)
__device__ __align__(16) __half g_h16[NN * D_H];   // fp16 copy of h (GEMM A input)
__device__ __align__(16) __half g_hpf[NN * D_H];   // fp16 h@W (aggregation gathers)
__device__ float g_es[NN];
__device__ float g_ed[NN];
__device__ int   g_deg[NN];
__device__ int   g_start[NN];
__device__ int   g_cur[NN];
__device__ int   g_total;
__device__ int   g_csrc[EE];                       // compact CSR-by-dst source ids

__device__ __forceinline__ float leaky(float x) {
    return x >= 0.f ? x : SLOPE * x;
}

__device__ __forceinline__ int load_idx2(const void* p, long long i, int is64) {
    return is64 ? (int)((const long long*)p)[i] : ((const int*)p)[i];
}

// Per-block index-dtype probe (warp ballot into shared flag)
__device__ __forceinline__ void probe_is64(const void* ei, int* flag) {
    if (threadIdx.x < 32) {
        const int* w = (const int*)ei;
        int lane = threadIdx.x;
        int nz = (w[2 * lane + 1] != 0) | (w[2 * (lane + 32) + 1] != 0);
        unsigned bal = __ballot_sync(0xffffffffu, nz);
        if (lane == 0) *flag = (bal == 0u);
    }
}

// pack two floats as f16x2 (one cvt instruction)
__device__ __forceinline__ uint32_t pack_f16(float a, float b) {
    half2 h = __floats2half2_rn(a, b);
    return *(uint32_t*)&h;
}

// m16n8k16 fp16 MMA, fp32 accumulate
__device__ __forceinline__ void mma_f16(float c[4], const uint32_t a[4],
                                        uint32_t b0, uint32_t b1) {
    asm volatile(
        "mma.sync.aligned.m16n8k16.row.col.f32.f16.f16.f32 "
        "{%0,%1,%2,%3}, {%4,%5,%6,%7}, {%8,%9}, {%0,%1,%2,%3};\n"
        : "+f"(c[0]), "+f"(c[1]), "+f"(c[2]), "+f"(c[3])
        : "r"(a[0]), "r"(a[1]), "r"(a[2]), "r"(a[3]), "r"(b0), "r"(b1));
}

__device__ __forceinline__ void cp_async16(uint32_t dst, const void* src, int sz) {
    asm volatile("cp.async.cg.shared.global [%0], [%1], 16, %2;"
                 :: "r"(dst), "l"(src), "r"(sz));
}
__device__ __forceinline__ void cp_commit() {
    asm volatile("cp.async.commit_group;");
}
__device__ __forceinline__ void cp_wait2() {
    asm volatile("cp.async.wait_group 2;");
}

// ---------------------------------------------------------------------------
// Compact CSR build: hist -> alloc -> scatter (g_deg pre-zeroed)
// ---------------------------------------------------------------------------
__global__ void k_hist(const void* __restrict__ ei) {
    __shared__ int s64;
    probe_is64(ei, &s64);
    __syncthreads();
    int e = blockIdx.x * blockDim.x + threadIdx.x;
    if (e < EE) {
        int d = load_idx2(ei, (long long)EE + e, s64);
        if ((unsigned)d < NN) atomicAdd(&g_deg[d], 1);
    }
}

__global__ void k_alloc() {
    int i = blockIdx.x * blockDim.x + threadIdx.x;
    if (i < NN) {
        int dg = g_deg[i];
        int st = atomicAdd(&g_total, dg);
        g_start[i] = st;
        g_cur[i]   = st;
    }
}

__global__ void k_scatter(const void* __restrict__ ei) {
    __shared__ int s64;
    probe_is64(ei, &s64);
    __syncthreads();
    int e = blockIdx.x * blockDim.x + threadIdx.x;
    if (e < EE) {
        int s = load_idx2(ei, e, s64);
        int d = load_idx2(ei, (long long)EE + e, s64);
        if ((unsigned)d < NN && (unsigned)s < NN) {
            int pos = atomicAdd(&g_cur[d], 1);
            g_csrc[pos] = s;
        }
    }
}

// ---------------------------------------------------------------------------
// k_mma_x: g_h = x @ W1 + b1 (fp32 out) + g_h16 (fp16 copy).
// R14 body: block 64x128, 8 warps (2x4), warp tile 32x32, BK=16,
// register-staged double buffer, scalar LDS fragment loads.
// ---------------------------------------------------------------------------
#define PAD_A 72
#define PAD_B 136

__global__ void __launch_bounds__(256, 4) k_mma_x(const float* __restrict__ A,
                                                  const float* __restrict__ B,
                                                  const float* __restrict__ bias) {
    __shared__ uint32_t Ah[2][8][PAD_A];   // [buf][k-pair][m]
    __shared__ uint32_t Bh[2][8][PAD_B];   // [buf][k-pair][n]

    const int tid  = threadIdx.x;
    const int warp = tid >> 5, lane = tid & 31;
    const int wm = warp >> 2, wn = warp & 3;
    const int gid = lane >> 2, tig = lane & 3;
    const int brow = blockIdx.x * 64;
    const int M = NN;

    const int a_r  = tid & 63;
    const int a_kq = (tid >> 6) * 4;
    const int b_bp = tid >> 5;
    const int b_n  = (tid & 31) * 4;

    float acc[2][4][4];
    #pragma unroll
    for (int mt = 0; mt < 2; mt++)
        #pragma unroll
        for (int nt = 0; nt < 4; nt++)
            #pragma unroll
            for (int c = 0; c < 4; c++) acc[mt][nt][c] = 0.f;

    float4 av, bv0, bv1;

    auto load_chunk = [&](int kc) {
        int g0 = brow + a_r;
        av = (g0 < M) ? *(const float4*)&A[(size_t)g0 * 128 + kc + a_kq]
                      : make_float4(0.f, 0.f, 0.f, 0.f);
        const float* B0 = &B[(size_t)(kc + 2 * b_bp) * 128 + b_n];
        bv0 = *(const float4*)B0;
        bv1 = *(const float4*)(B0 + 128);
    };

    auto store_chunk = [&](int buf) {
        Ah[buf][a_kq / 2][a_r]     = pack_f16(av.x, av.y);
        Ah[buf][a_kq / 2 + 1][a_r] = pack_f16(av.z, av.w);
        uint4 hq;
        uint32_t* hp_ = (uint32_t*)&hq;
        hp_[0] = pack_f16(bv0.x, bv1.x);
        hp_[1] = pack_f16(bv0.y, bv1.y);
        hp_[2] = pack_f16(bv0.z, bv1.z);
        hp_[3] = pack_f16(bv0.w, bv1.w);
        *(uint4*)&Bh[buf][b_bp][b_n] = hq;
    };

    load_chunk(0);
    store_chunk(0);
    __syncthreads();

    #pragma unroll 1
    for (int c = 0; c < 8; c++) {
        const int cur = c & 1;
        if (c < 7) load_chunk((c + 1) * 16);
        {
            uint32_t ah[2][4];
            #pragma unroll
            for (int mt = 0; mt < 2; mt++) {
                int m0 = wm * 32 + mt * 16 + gid;
                ah[mt][0] = Ah[cur][tig][m0];     ah[mt][1] = Ah[cur][tig][m0 + 8];
                ah[mt][2] = Ah[cur][tig + 4][m0]; ah[mt][3] = Ah[cur][tig + 4][m0 + 8];
            }
            #pragma unroll
            for (int nt = 0; nt < 4; nt++) {
                int n0 = wn * 32 + nt * 8 + gid;
                uint32_t bh0 = Bh[cur][tig][n0], bh1 = Bh[cur][tig + 4][n0];
                #pragma unroll
                for (int mt = 0; mt < 2; mt++)
                    mma_f16(acc[mt][nt], ah[mt], bh0, bh1);
            }
        }
        if (c < 7) store_chunk(cur ^ 1);
        __syncthreads();
    }

    #pragma unroll
    for (int mt = 0; mt < 2; mt++) {
        int r0 = brow + wm * 32 + mt * 16 + gid;
        #pragma unroll
        for (int nt = 0; nt < 4; nt++) {
            int c0 = wn * 32 + nt * 8 + 2 * tig;
            float b0v = bias[c0], b1v = bias[c0 + 1];
            float v00 = acc[mt][nt][0] + b0v, v01 = acc[mt][nt][1] + b1v;
            float v10 = acc[mt][nt][2] + b0v, v11 = acc[mt][nt][3] + b1v;
            if (r0 < M) {
                *(float2*)&g_h[(size_t)r0 * 128 + c0] = make_float2(v00, v01);
                *(uint32_t*)&g_h16[(size_t)r0 * 128 + c0] = pack_f16(v00, v01);
            }
            if (r0 + 8 < M) {
                *(float2*)&g_h[(size_t)(r0 + 8) * 128 + c0] = make_float2(v10, v11);
                *(uint32_t*)&g_h16[(size_t)(r0 + 8) * 128 + c0] = pack_f16(v10, v11);
            }
        }
    }
}

// ---------------------------------------------------------------------------
// k_mma_h: g_hpf = fp16(h @ Wg[l]) + fused es/ed.
// A read as fp16 from g_h16 via 4-stage cp.async pipeline (DRAM latency
// hidden, traffic halved, no A cvt). B register-staged as before.
// A smem layout [m][k-pair], 48B row stride (conflict-free quad pattern).
// ---------------------------------------------------------------------------
#define A_ST 12                       // uint32 per A row (48 B)
#define A_STAGE_BYTES (64 * A_ST * 4) // 3072 B per stage

__global__ void __launch_bounds__(256, 4) k_mma_h(const float* __restrict__ B,
                                                  const float* __restrict__ asrc,
                                                  const float* __restrict__ adst) {
    __shared__ uint32_t As[4][64][A_ST];   // [stage][m][k-pair]
    __shared__ uint32_t Bh[2][8][PAD_B];   // [buf][k-pair][n]
    __shared__ float es_s[64], ed_s[64];

    const int tid  = threadIdx.x;
    const int warp = tid >> 5, lane = tid & 31;
    const int wm = warp >> 2, wn = warp & 3;
    const int gid = lane >> 2, tig = lane & 3;
    const int brow = blockIdx.x * 64;
    const int M = NN;

    if (tid < 64) { es_s[tid] = 0.f; ed_s[tid] = 0.f; }

    const int b_bp = tid >> 5;
    const int b_n  = (tid & 31) * 4;

    const uint32_t as_base = (uint32_t)__cvta_generic_to_shared(&As[0][0][0]);
    const int cp_r  = tid >> 1;      // row 0..63 (tid<128)
    const int cp_hf = tid & 1;       // 16B half of the 32B row

    // issue stage for chunk c (guarded), always commit (uniform group count)
    auto cp_stage = [&](int c) {
        if (c < 8 && tid < 128) {
            int grow = brow + cp_r;
            uint32_t dst = as_base + (c & 3) * A_STAGE_BYTES + cp_r * 48 + cp_hf * 16;
            const __half* src = &g_h16[(size_t)grow * 128 + c * 16 + cp_hf * 8];
            cp_async16(dst, src, (grow < M) ? 16 : 0);
        }
        cp_commit();
    };

    float4 bv0, bv1;
    auto load_B = [&](int kc) {
        const float* B0 = &B[(size_t)(kc + 2 * b_bp) * 128 + b_n];
        bv0 = *(const float4*)B0;
        bv1 = *(const float4*)(B0 + 128);
    };
    auto store_B = [&](int buf) {
        uint4 hq;
        uint32_t* hp_ = (uint32_t*)&hq;
        hp_[0] = pack_f16(bv0.x, bv1.x);
        hp_[1] = pack_f16(bv0.y, bv1.y);
        hp_[2] = pack_f16(bv0.z, bv1.z);
        hp_[3] = pack_f16(bv0.w, bv1.w);
        *(uint4*)&Bh[buf][b_bp][b_n] = hq;
    };

    float acc[2][4][4];
    #pragma unroll
    for (int mt = 0; mt < 2; mt++)
        #pragma unroll
        for (int nt = 0; nt < 4; nt++)
            #pragma unroll
            for (int c = 0; c < 4; c++) acc[mt][nt][c] = 0.f;

    // prologue: A chunks 0..2 in flight, B chunk 0 staged
    cp_stage(0); cp_stage(1); cp_stage(2);
    load_B(0);
    store_B(0);
    cp_wait2();            // chunk 0 complete (2 pending)
    __syncthreads();

    #pragma unroll 1
    for (int c = 0; c < 8; c++) {
        const int cur = c & 1;
        const int st  = c & 3;
        cp_stage(c + 3);                    // keep 3 A chunks in flight
        if (c < 7) load_B((c + 1) * 16);

        {
            uint32_t ah[2][4];
            #pragma unroll
            for (int mt = 0; mt < 2; mt++) {
                int m0 = wm * 32 + mt * 16 + gid;
                ah[mt][0] = As[st][m0][tig];         ah[mt][1] = As[st][m0 + 8][tig];
                ah[mt][2] = As[st][m0][tig + 4];     ah[mt][3] = As[st][m0 + 8][tig + 4];
            }
            #pragma unroll
            for (int nt = 0; nt < 4; nt++) {
                int n0 = wn * 32 + nt * 8 + gid;
                uint32_t bh0 = Bh[cur][tig][n0], bh1 = Bh[cur][tig + 4][n0];
                #pragma unroll
                for (int mt = 0; mt < 2; mt++)
                    mma_f16(acc[mt][nt], ah[mt], bh0, bh1);
            }
        }

        if (c < 7) store_B(cur ^ 1);
        cp_wait2();                         // chunk c+1 complete
        __syncthreads();
    }

    float as_v[4][2], ad_v[4][2];
    #pragma unroll
    for (int nt = 0; nt < 4; nt++) {
        int c0 = wn * 32 + nt * 8 + 2 * tig;
        as_v[nt][0] = asrc[c0]; as_v[nt][1] = asrc[c0 + 1];
        ad_v[nt][0] = adst[c0]; ad_v[nt][1] = adst[c0 + 1];
    }

    #pragma unroll
    for (int mt = 0; mt < 2; mt++) {
        int r0 = brow + wm * 32 + mt * 16 + gid;
        float pe0 = 0.f, pe1 = 0.f, pd0 = 0.f, pd1 = 0.f;
        #pragma unroll
        for (int nt = 0; nt < 4; nt++) {
            int c0 = wn * 32 + nt * 8 + 2 * tig;
            float v00 = acc[mt][nt][0], v01 = acc[mt][nt][1];
            float v10 = acc[mt][nt][2], v11 = acc[mt][nt][3];
            if (r0 < M)     *(uint32_t*)&g_hpf[(size_t)r0 * 128 + c0]       = pack_f16(v00, v01);
            if (r0 + 8 < M) *(uint32_t*)&g_hpf[(size_t)(r0 + 8) * 128 + c0] = pack_f16(v10, v11);
            pe0 += v00 * as_v[nt][0] + v01 * as_v[nt][1];
            pe1 += v10 * as_v[nt][0] + v11 * as_v[nt][1];
            pd0 += v00 * ad_v[nt][0] + v01 * ad_v[nt][1];
            pd1 += v10 * ad_v[nt][0] + v11 * ad_v[nt][1];
        }
        #pragma unroll
        for (int o = 1; o <= 2; o <<= 1) {
            pe0 += __shfl_xor_sync(0xffffffffu, pe0, o);
            pe1 += __shfl_xor_sync(0xffffffffu, pe1, o);
            pd0 += __shfl_xor_sync(0xffffffffu, pd0, o);
            pd1 += __shfl_xor_sync(0xffffffffu, pd1, o);
        }
        if (tig == 0) {
            int lr = wm * 32 + mt * 16 + gid;
            atomicAdd(&es_s[lr], pe0);     atomicAdd(&es_s[lr + 8], pe1);
            atomicAdd(&ed_s[lr], pd0);     atomicAdd(&ed_s[lr + 8], pd1);
        }
    }

    __syncthreads();
    if (tid < 64 && brow + tid < M) {
        g_es[brow + tid] = es_s[tid];
        g_ed[brow + tid] = ed_s[tid];
    }
}

// ---------------------------------------------------------------------------
// GAT aggregation (warp per destination node, compact CSR) — single pass,
// no max-shift softmax, fp16 gather, x4 batched loads. Writes fp32 g_h and
// fp16 g_h16 (next layer's GEMM A input).
// ---------------------------------------------------------------------------
__global__ void k_gat_aggr(const float* __restrict__ bg) {
    int warp = (blockIdx.x * blockDim.x + threadIdx.x) >> 5;
    int lane = threadIdx.x & 31;
    if (warp >= NN) return;
    const int d = warp;
    const int lo = g_start[d], hi = lo + g_deg[d];
    const float ed_d = g_ed[d];
    const float e_self = leaky(g_es[d] + ed_d);

    float ex_self = expf(e_self);
    float z = ex_self;
    uint2 sv = *(const uint2*)&g_hpf[(size_t)d * 128 + 4 * lane];
    float2 s0 = __half22float2(*(half2*)&sv.x);
    float2 s1 = __half22float2(*(half2*)&sv.y);
    float ax = ex_self * s0.x, ay = ex_self * s0.y;
    float az = ex_self * s1.x, aw = ex_self * s1.y;

    const size_t fo = 4 * lane;
    int j = lo;

    for (; j + 4 <= hi; j += 4) {
        int i0 = g_csrc[j],     i1 = g_csrc[j + 1];
        int i2 = g_csrc[j + 2], i3 = g_csrc[j + 3];
        float e0 = g_es[i0], e1 = g_es[i1], e2 = g_es[i2], e3 = g_es[i3];
        uint2 w0 = *(const uint2*)&g_hpf[(size_t)i0 * 128 + fo];
        uint2 w1 = *(const uint2*)&g_hpf[(size_t)i1 * 128 + fo];
        uint2 w2 = *(const uint2*)&g_hpf[(size_t)i2 * 128 + fo];
        uint2 w3 = *(const uint2*)&g_hpf[(size_t)i3 * 128 + fo];

        float x0 = expf(leaky(e0 + ed_d));
        float x1 = expf(leaky(e1 + ed_d));
        float x2 = expf(leaky(e2 + ed_d));
        float x3 = expf(leaky(e3 + ed_d));
        z += (x0 + x1) + (x2 + x3);

        float2 a0 = __half22float2(*(half2*)&w0.x), b0 = __half22float2(*(half2*)&w0.y);
        float2 a1 = __half22float2(*(half2*)&w1.x), b1 = __half22float2(*(half2*)&w1.y);
        float2 a2 = __half22float2(*(half2*)&w2.x), b2 = __half22float2(*(half2*)&w2.y);
        float2 a3 = __half22float2(*(half2*)&w3.x), b3 = __half22float2(*(half2*)&w3.y);

        ax = fmaf(x0, a0.x, ax); ay = fmaf(x0, a0.y, ay);
        az = fmaf(x0, b0.x, az); aw = fmaf(x0, b0.y, aw);
        ax = fmaf(x1, a1.x, ax); ay = fmaf(x1, a1.y, ay);
        az = fmaf(x1, b1.x, az); aw = fmaf(x1, b1.y, aw);
        ax = fmaf(x2, a2.x, ax); ay = fmaf(x2, a2.y, ay);
        az = fmaf(x2, b2.x, az); aw = fmaf(x2, b2.y, aw);
        ax = fmaf(x3, a3.x, ax); ay = fmaf(x3, a3.y, ay);
        az = fmaf(x3, b3.x, az); aw = fmaf(x3, b3.y, aw);
    }

    for (; j < hi; ++j) {
        int s = g_csrc[j];
        float ex = expf(leaky(g_es[s] + ed_d));
        z += ex;
        uint2 wv = *(const uint2*)&g_hpf[(size_t)s * 128 + fo];
        float2 w0 = __half22float2(*(half2*)&wv.x);
        float2 w1 = __half22float2(*(half2*)&wv.y);
        ax = fmaf(ex, w0.x, ax);
        ay = fmaf(ex, w0.y, ay);
        az = fmaf(ex, w1.x, az);
        aw = fmaf(ex, w1.y, aw);
    }
    const float invz = 1.0f / z;

    float4* h4 = (float4*)g_h;
    float4 b = ((const float4*)bg)[lane];
    float4 hin = h4[(size_t)d * 32 + lane];
    float4 o;
    o.x = fmaxf(fmaf(ax, invz, b.x), 0.f) + hin.x;
    o.y = fmaxf(fmaf(ay, invz, b.y), 0.f) + hin.y;
    o.z = fmaxf(fmaf(az, invz, b.z), 0.f) + hin.z;
    o.w = fmaxf(fmaf(aw, invz, b.w), 0.f) + hin.w;
    h4[(size_t)d * 32 + lane] = o;
    // fp16 copy for the next layer's GEMM A (coalesced 8B/lane)
    *(uint2*)&g_h16[(size_t)d * 128 + fo] =
        make_uint2(pack_f16(o.x, o.y), pack_f16(o.z, o.w));
}

// ---------------------------------------------------------------------------
// Fused pool + final projection; re-zeroes g_deg/g_total for the next run.
// ---------------------------------------------------------------------------
__global__ void k_poolfinal(const void* __restrict__ ei,
                            const void* __restrict__ batch,
                            const float* __restrict__ W2,
                            const float* __restrict__ b2,
                            float* __restrict__ out) {
    __shared__ float ps[128];
    __shared__ int s_lo, s_hi, s64;
    const int g = blockIdx.x;
    const int tid = threadIdx.x;
    probe_is64(ei, &s64);
    __syncthreads();
    if (tid == 0) {
        int lo = 0, hi = NN;
        while (lo < hi) { int mid = (lo + hi) >> 1; if (load_idx2(batch, mid, s64) < g) lo = mid + 1; else hi = mid; }
        s_lo = lo;
        lo = 0; hi = NN;
        int g1 = g + 1;
        while (lo < hi) { int mid = (lo + hi) >> 1; if (load_idx2(batch, mid, s64) < g1) lo = mid + 1; else hi = mid; }
        s_hi = lo;
    }
    __syncthreads();
    float acc = 0.f;
    for (int i = s_lo; i < s_hi; ++i) acc += g_h[(size_t)i * 128 + tid];
    ps[tid] = acc;
    __syncthreads();
    if (tid < 64) {
        float o = b2[tid];
        #pragma unroll 8
        for (int k = 0; k < 128; ++k)
            o = fmaf(ps[k], W2[k * 64 + tid], o);
        out[g * 64 + tid] = o;
    }
    // reset CSR counters for the next invocation
    for (int i = g * 128 + tid; i < NN; i += NG * 128) g_deg[i] = 0;
    if (g == 0 && tid == 0) g_total = 0;
}

// ---------------------------------------------------------------------------
// Launch (11 kernels)
// ---------------------------------------------------------------------------
extern "C" void kernel_launch(void* const* d_in, const int* in_sizes, int n_in,
                              void* d_out, int out_size) {
    const float* x     = (const float*)d_in[0];
    const void*  ei    = d_in[1];
    const void*  batch = d_in[2];
    const float* W1    = (const float*)d_in[3];
    const float* b1    = (const float*)d_in[4];
    const float* Wg    = (const float*)d_in[5];
    const float* asrc  = (const float*)d_in[6];
    const float* adst  = (const float*)d_in[7];
    const float* bg    = (const float*)d_in[8];
    const float* W2    = (const float*)d_in[9];
    const float* b2    = (const float*)d_in[10];
    float*       out   = (float*)d_out;

    k_hist<<<(EE + 255) / 256, 256>>>(ei);
    k_alloc<<<(NN + 255) / 256, 256>>>();
    k_scatter<<<(EE + 255) / 256, 256>>>(ei);

    const int gemm_blocks = (NN + 63) / 64;
    const int node_warp_blocks = (NN * 32 + 255) / 256;

    k_mma_x<<<gemm_blocks, 256>>>(x, W1, b1);

    for (int l = 0; l < NLAYERS; ++l) {
        k_mma_h<<<gemm_blocks, 256>>>(Wg + (size_t)l * 128 * 128,
                                      asrc + l * 128, adst + l * 128);
        k_gat_aggr<<<node_warp_blocks, 256>>>(bg + l * 128);
    }

    k_poolfinal<<<NG, 128>>>(ei, batch, W2, b2, out);
}

// round 17
// speedup vs baseline: 1.0637x; 1.0278x over previous
#include <cuda_runtime.h>
#include <cuda_bf16.h>
#include <cuda_fp16.h>
#include <math.h>
#include <stdint.h>

// Problem constants (match reference)
#define NN      50000
#define EE      600000
#define D_IN    128
#define D_H     128
#define D_OUT   64
#define NLAYERS 3
#define NG      64
#define SLOPE   0.2f

// ---------------------------------------------------------------------------
// Device scratch (g_deg/g_total statically zeroed; re-zeroed by k_poolfinal)
// ---------------------------------------------------------------------------
__device__ __align__(16) float  g_h  [NN * D_H];   // fp32 features (residual/pool)
__device__ __align__(16) __half g_h16[NN * D_H];   // fp16 copy of h (GEMM A input)
__device__ __align__(16) __half g_hpf[NN * D_H];   // fp16 h@W (aggregation gathers)
__device__ float g_es[NN];
__device__ float g_ed[NN];
__device__ int   g_deg[NN];
__device__ int   g_start[NN];
__device__ int   g_cur[NN];
__device__ int   g_total;
__device__ int   g_csrc[EE];                       // compact CSR-by-dst source ids

__device__ __forceinline__ float leaky(float x) {
    return x >= 0.f ? x : SLOPE * x;
}

__device__ __forceinline__ int load_idx2(const void* p, long long i, int is64) {
    return is64 ? (int)((const long long*)p)[i] : ((const int*)p)[i];
}

// Per-block index-dtype probe (warp ballot into shared flag)
__device__ __forceinline__ void probe_is64(const void* ei, int* flag) {
    if (threadIdx.x < 32) {
        const int* w = (const int*)ei;
        int lane = threadIdx.x;
        int nz = (w[2 * lane + 1] != 0) | (w[2 * (lane + 32) + 1] != 0);
        unsigned bal = __ballot_sync(0xffffffffu, nz);
        if (lane == 0) *flag = (bal == 0u);
    }
}

// pack two floats as f16x2 (one cvt instruction)
__device__ __forceinline__ uint32_t pack_f16(float a, float b) {
    half2 h = __floats2half2_rn(a, b);
    return *(uint32_t*)&h;
}

// m16n8k16 fp16 MMA, fp32 accumulate
__device__ __forceinline__ void mma_f16(float c[4], const uint32_t a[4],
                                        uint32_t b0, uint32_t b1) {
    asm volatile(
        "mma.sync.aligned.m16n8k16.row.col.f32.f16.f16.f32 "
        "{%0,%1,%2,%3}, {%4,%5,%6,%7}, {%8,%9}, {%0,%1,%2,%3};\n"
        : "+f"(c[0]), "+f"(c[1]), "+f"(c[2]), "+f"(c[3])
        : "r"(a[0]), "r"(a[1]), "r"(a[2]), "r"(a[3]), "r"(b0), "r"(b1));
}

__device__ __forceinline__ void cp_async16(uint32_t dst, const void* src, int sz) {
    asm volatile("cp.async.cg.shared.global [%0], [%1], 16, %2;"
                 :: "r"(dst), "l"(src), "r"(sz));
}
__device__ __forceinline__ void cp_commit() {
    asm volatile("cp.async.commit_group;");
}
__device__ __forceinline__ void cp_wait2() {
    asm volatile("cp.async.wait_group 2;");
}

// ---------------------------------------------------------------------------
// Compact CSR build: hist -> alloc -> scatter (g_deg pre-zeroed)
// ---------------------------------------------------------------------------
__global__ void k_hist(const void* __restrict__ ei) {
    __shared__ int s64;
    probe_is64(ei, &s64);
    __syncthreads();
    int e = blockIdx.x * blockDim.x + threadIdx.x;
    if (e < EE) {
        int d = load_idx2(ei, (long long)EE + e, s64);
        if ((unsigned)d < NN) atomicAdd(&g_deg[d], 1);
    }
}

__global__ void k_alloc() {
    int i = blockIdx.x * blockDim.x + threadIdx.x;
    if (i < NN) {
        int dg = g_deg[i];
        int st = atomicAdd(&g_total, dg);
        g_start[i] = st;
        g_cur[i]   = st;
    }
}

__global__ void k_scatter(const void* __restrict__ ei) {
    __shared__ int s64;
    probe_is64(ei, &s64);
    __syncthreads();
    int e = blockIdx.x * blockDim.x + threadIdx.x;
    if (e < EE) {
        int s = load_idx2(ei, e, s64);
        int d = load_idx2(ei, (long long)EE + e, s64);
        if ((unsigned)d < NN && (unsigned)s < NN) {
            int pos = atomicAdd(&g_cur[d], 1);
            g_csrc[pos] = s;
        }
    }
}

// ---------------------------------------------------------------------------
// k_mma_x: g_h = x @ W1 + b1 (fp32 out) + g_h16 (fp16 copy).
// Block 64x128, 8 warps (2x4), warp tile 32x32, BK=16, register-staged
// double buffer, scalar LDS fragment loads (R14 body).
// ---------------------------------------------------------------------------
#define PAD_A 72
#define PAD_B 136

__global__ void __launch_bounds__(256, 4) k_mma_x(const float* __restrict__ A,
                                                  const float* __restrict__ B,
                                                  const float* __restrict__ bias) {
    __shared__ uint32_t Ah[2][8][PAD_A];   // [buf][k-pair][m]
    __shared__ uint32_t Bh[2][8][PAD_B];   // [buf][k-pair][n]

    const int tid  = threadIdx.x;
    const int warp = tid >> 5, lane = tid & 31;
    const int wm = warp >> 2, wn = warp & 3;
    const int gid = lane >> 2, tig = lane & 3;
    const int brow = blockIdx.x * 64;
    const int M = NN;

    const int a_r  = tid & 63;
    const int a_kq = (tid >> 6) * 4;
    const int b_bp = tid >> 5;
    const int b_n  = (tid & 31) * 4;

    float acc[2][4][4];
    #pragma unroll
    for (int mt = 0; mt < 2; mt++)
        #pragma unroll
        for (int nt = 0; nt < 4; nt++)
            #pragma unroll
            for (int c = 0; c < 4; c++) acc[mt][nt][c] = 0.f;

    float4 av, bv0, bv1;

    auto load_chunk = [&](int kc) {
        int g0 = brow + a_r;
        av = (g0 < M) ? *(const float4*)&A[(size_t)g0 * 128 + kc + a_kq]
                      : make_float4(0.f, 0.f, 0.f, 0.f);
        const float* B0 = &B[(size_t)(kc + 2 * b_bp) * 128 + b_n];
        bv0 = *(const float4*)B0;
        bv1 = *(const float4*)(B0 + 128);
    };

    auto store_chunk = [&](int buf) {
        Ah[buf][a_kq / 2][a_r]     = pack_f16(av.x, av.y);
        Ah[buf][a_kq / 2 + 1][a_r] = pack_f16(av.z, av.w);
        uint4 hq;
        uint32_t* hp_ = (uint32_t*)&hq;
        hp_[0] = pack_f16(bv0.x, bv1.x);
        hp_[1] = pack_f16(bv0.y, bv1.y);
        hp_[2] = pack_f16(bv0.z, bv1.z);
        hp_[3] = pack_f16(bv0.w, bv1.w);
        *(uint4*)&Bh[buf][b_bp][b_n] = hq;
    };

    load_chunk(0);
    store_chunk(0);
    __syncthreads();

    #pragma unroll 1
    for (int c = 0; c < 8; c++) {
        const int cur = c & 1;
        if (c < 7) load_chunk((c + 1) * 16);
        {
            uint32_t ah[2][4];
            #pragma unroll
            for (int mt = 0; mt < 2; mt++) {
                int m0 = wm * 32 + mt * 16 + gid;
                ah[mt][0] = Ah[cur][tig][m0];     ah[mt][1] = Ah[cur][tig][m0 + 8];
                ah[mt][2] = Ah[cur][tig + 4][m0]; ah[mt][3] = Ah[cur][tig + 4][m0 + 8];
            }
            #pragma unroll
            for (int nt = 0; nt < 4; nt++) {
                int n0 = wn * 32 + nt * 8 + gid;
                uint32_t bh0 = Bh[cur][tig][n0], bh1 = Bh[cur][tig + 4][n0];
                #pragma unroll
                for (int mt = 0; mt < 2; mt++)
                    mma_f16(acc[mt][nt], ah[mt], bh0, bh1);
            }
        }
        if (c < 7) store_chunk(cur ^ 1);
        __syncthreads();
    }

    #pragma unroll
    for (int mt = 0; mt < 2; mt++) {
        int r0 = brow + wm * 32 + mt * 16 + gid;
        #pragma unroll
        for (int nt = 0; nt < 4; nt++) {
            int c0 = wn * 32 + nt * 8 + 2 * tig;
            float b0v = bias[c0], b1v = bias[c0 + 1];
            float v00 = acc[mt][nt][0] + b0v, v01 = acc[mt][nt][1] + b1v;
            float v10 = acc[mt][nt][2] + b0v, v11 = acc[mt][nt][3] + b1v;
            if (r0 < M) {
                *(float2*)&g_h[(size_t)r0 * 128 + c0] = make_float2(v00, v01);
                *(uint32_t*)&g_h16[(size_t)r0 * 128 + c0] = pack_f16(v00, v01);
            }
            if (r0 + 8 < M) {
                *(float2*)&g_h[(size_t)(r0 + 8) * 128 + c0] = make_float2(v10, v11);
                *(uint32_t*)&g_h16[(size_t)(r0 + 8) * 128 + c0] = pack_f16(v10, v11);
            }
        }
    }
}

// ---------------------------------------------------------------------------
// k_mma_h: g_hpf = fp16(h @ Wg[l]) + fused es/ed.
// A via 4-stage cp.async pipeline from g_h16; B register-staged (R16 body).
// ---------------------------------------------------------------------------
#define A_ST 12                       // uint32 per A row (48 B)
#define A_STAGE_BYTES (64 * A_ST * 4) // 3072 B per stage

__global__ void __launch_bounds__(256, 4) k_mma_h(const float* __restrict__ B,
                                                  const float* __restrict__ asrc,
                                                  const float* __restrict__ adst) {
    __shared__ uint32_t As[4][64][A_ST];   // [stage][m][k-pair]
    __shared__ uint32_t Bh[2][8][PAD_B];   // [buf][k-pair][n]
    __shared__ float es_s[64], ed_s[64];

    const int tid  = threadIdx.x;
    const int warp = tid >> 5, lane = tid & 31;
    const int wm = warp >> 2, wn = warp & 3;
    const int gid = lane >> 2, tig = lane & 3;
    const int brow = blockIdx.x * 64;
    const int M = NN;

    if (tid < 64) { es_s[tid] = 0.f; ed_s[tid] = 0.f; }

    const int b_bp = tid >> 5;
    const int b_n  = (tid & 31) * 4;

    const uint32_t as_base = (uint32_t)__cvta_generic_to_shared(&As[0][0][0]);
    const int cp_r  = tid >> 1;      // row 0..63 (tid<128)
    const int cp_hf = tid & 1;       // 16B half of the 32B row

    auto cp_stage = [&](int c) {
        if (c < 8 && tid < 128) {
            int grow = brow + cp_r;
            uint32_t dst = as_base + (c & 3) * A_STAGE_BYTES + cp_r * 48 + cp_hf * 16;
            const __half* src = &g_h16[(size_t)grow * 128 + c * 16 + cp_hf * 8];
            cp_async16(dst, src, (grow < M) ? 16 : 0);
        }
        cp_commit();
    };

    float4 bv0, bv1;
    auto load_B = [&](int kc) {
        const float* B0 = &B[(size_t)(kc + 2 * b_bp) * 128 + b_n];
        bv0 = *(const float4*)B0;
        bv1 = *(const float4*)(B0 + 128);
    };
    auto store_B = [&](int buf) {
        uint4 hq;
        uint32_t* hp_ = (uint32_t*)&hq;
        hp_[0] = pack_f16(bv0.x, bv1.x);
        hp_[1] = pack_f16(bv0.y, bv1.y);
        hp_[2] = pack_f16(bv0.z, bv1.z);
        hp_[3] = pack_f16(bv0.w, bv1.w);
        *(uint4*)&Bh[buf][b_bp][b_n] = hq;
    };

    float acc[2][4][4];
    #pragma unroll
    for (int mt = 0; mt < 2; mt++)
        #pragma unroll
        for (int nt = 0; nt < 4; nt++)
            #pragma unroll
            for (int c = 0; c < 4; c++) acc[mt][nt][c] = 0.f;

    cp_stage(0); cp_stage(1); cp_stage(2);
    load_B(0);
    store_B(0);
    cp_wait2();
    __syncthreads();

    #pragma unroll 1
    for (int c = 0; c < 8; c++) {
        const int cur = c & 1;
        const int st  = c & 3;
        cp_stage(c + 3);
        if (c < 7) load_B((c + 1) * 16);

        {
            uint32_t ah[2][4];
            #pragma unroll
            for (int mt = 0; mt < 2; mt++) {
                int m0 = wm * 32 + mt * 16 + gid;
                ah[mt][0] = As[st][m0][tig];         ah[mt][1] = As[st][m0 + 8][tig];
                ah[mt][2] = As[st][m0][tig + 4];     ah[mt][3] = As[st][m0 + 8][tig + 4];
            }
            #pragma unroll
            for (int nt = 0; nt < 4; nt++) {
                int n0 = wn * 32 + nt * 8 + gid;
                uint32_t bh0 = Bh[cur][tig][n0], bh1 = Bh[cur][tig + 4][n0];
                #pragma unroll
                for (int mt = 0; mt < 2; mt++)
                    mma_f16(acc[mt][nt], ah[mt], bh0, bh1);
            }
        }

        if (c < 7) store_B(cur ^ 1);
        cp_wait2();
        __syncthreads();
    }

    float as_v[4][2], ad_v[4][2];
    #pragma unroll
    for (int nt = 0; nt < 4; nt++) {
        int c0 = wn * 32 + nt * 8 + 2 * tig;
        as_v[nt][0] = asrc[c0]; as_v[nt][1] = asrc[c0 + 1];
        ad_v[nt][0] = adst[c0]; ad_v[nt][1] = adst[c0 + 1];
    }

    #pragma unroll
    for (int mt = 0; mt < 2; mt++) {
        int r0 = brow + wm * 32 + mt * 16 + gid;
        float pe0 = 0.f, pe1 = 0.f, pd0 = 0.f, pd1 = 0.f;
        #pragma unroll
        for (int nt = 0; nt < 4; nt++) {
            int c0 = wn * 32 + nt * 8 + 2 * tig;
            float v00 = acc[mt][nt][0], v01 = acc[mt][nt][1];
            float v10 = acc[mt][nt][2], v11 = acc[mt][nt][3];
            if (r0 < M)     *(uint32_t*)&g_hpf[(size_t)r0 * 128 + c0]       = pack_f16(v00, v01);
            if (r0 + 8 < M) *(uint32_t*)&g_hpf[(size_t)(r0 + 8) * 128 + c0] = pack_f16(v10, v11);
            pe0 += v00 * as_v[nt][0] + v01 * as_v[nt][1];
            pe1 += v10 * as_v[nt][0] + v11 * as_v[nt][1];
            pd0 += v00 * ad_v[nt][0] + v01 * ad_v[nt][1];
            pd1 += v10 * ad_v[nt][0] + v11 * ad_v[nt][1];
        }
        #pragma unroll
        for (int o = 1; o <= 2; o <<= 1) {
            pe0 += __shfl_xor_sync(0xffffffffu, pe0, o);
            pe1 += __shfl_xor_sync(0xffffffffu, pe1, o);
            pd0 += __shfl_xor_sync(0xffffffffu, pd0, o);
            pd1 += __shfl_xor_sync(0xffffffffu, pd1, o);
        }
        if (tig == 0) {
            int lr = wm * 32 + mt * 16 + gid;
            atomicAdd(&es_s[lr], pe0);     atomicAdd(&es_s[lr + 8], pe1);
            atomicAdd(&ed_s[lr], pd0);     atomicAdd(&ed_s[lr + 8], pd1);
        }
    }

    __syncthreads();
    if (tid < 64 && brow + tid < M) {
        g_es[brow + tid] = es_s[tid];
        g_ed[brow + tid] = ed_s[tid];
    }
}

// ---------------------------------------------------------------------------
// GAT aggregation (warp per destination node, compact CSR) — single pass,
// no max-shift softmax, fp16 gather, x4 batched loads. Writes fp32 g_h and
// fp16 g_h16 (next layer's GEMM A input).
// ---------------------------------------------------------------------------
__global__ void k_gat_aggr(const float* __restrict__ bg) {
    int warp = (blockIdx.x * blockDim.x + threadIdx.x) >> 5;
    int lane = threadIdx.x & 31;
    if (warp >= NN) return;
    const int d = warp;
    const int lo = g_start[d], hi = lo + g_deg[d];
    const float ed_d = g_ed[d];
    const float e_self = leaky(g_es[d] + ed_d);

    float ex_self = expf(e_self);
    float z = ex_self;
    uint2 sv = *(const uint2*)&g_hpf[(size_t)d * 128 + 4 * lane];
    float2 s0 = __half22float2(*(half2*)&sv.x);
    float2 s1 = __half22float2(*(half2*)&sv.y);
    float ax = ex_self * s0.x, ay = ex_self * s0.y;
    float az = ex_self * s1.x, aw = ex_self * s1.y;

    const size_t fo = 4 * lane;
    int j = lo;

    for (; j + 4 <= hi; j += 4) {
        int i0 = g_csrc[j],     i1 = g_csrc[j + 1];
        int i2 = g_csrc[j + 2], i3 = g_csrc[j + 3];
        float e0 = g_es[i0], e1 = g_es[i1], e2 = g_es[i2], e3 = g_es[i3];
        uint2 w0 = *(const uint2*)&g_hpf[(size_t)i0 * 128 + fo];
        uint2 w1 = *(const uint2*)&g_hpf[(size_t)i1 * 128 + fo];
        uint2 w2 = *(const uint2*)&g_hpf[(size_t)i2 * 128 + fo];
        uint2 w3 = *(const uint2*)&g_hpf[(size_t)i3 * 128 + fo];

        float x0 = expf(leaky(e0 + ed_d));
        float x1 = expf(leaky(e1 + ed_d));
        float x2 = expf(leaky(e2 + ed_d));
        float x3 = expf(leaky(e3 + ed_d));
        z += (x0 + x1) + (x2 + x3);

        float2 a0 = __half22float2(*(half2*)&w0.x), b0 = __half22float2(*(half2*)&w0.y);
        float2 a1 = __half22float2(*(half2*)&w1.x), b1 = __half22float2(*(half2*)&w1.y);
        float2 a2 = __half22float2(*(half2*)&w2.x), b2 = __half22float2(*(half2*)&w2.y);
        float2 a3 = __half22float2(*(half2*)&w3.x), b3 = __half22float2(*(half2*)&w3.y);

        ax = fmaf(x0, a0.x, ax); ay = fmaf(x0, a0.y, ay);
        az = fmaf(x0, b0.x, az); aw = fmaf(x0, b0.y, aw);
        ax = fmaf(x1, a1.x, ax); ay = fmaf(x1, a1.y, ay);
        az = fmaf(x1, b1.x, az); aw = fmaf(x1, b1.y, aw);
        ax = fmaf(x2, a2.x, ax); ay = fmaf(x2, a2.y, ay);
        az = fmaf(x2, b2.x, az); aw = fmaf(x2, b2.y, aw);
        ax = fmaf(x3, a3.x, ax); ay = fmaf(x3, a3.y, ay);
        az = fmaf(x3, b3.x, az); aw = fmaf(x3, b3.y, aw);
    }

    for (; j < hi; ++j) {
        int s = g_csrc[j];
        float ex = expf(leaky(g_es[s] + ed_d));
        z += ex;
        uint2 wv = *(const uint2*)&g_hpf[(size_t)s * 128 + fo];
        float2 w0 = __half22float2(*(half2*)&wv.x);
        float2 w1 = __half22float2(*(half2*)&wv.y);
        ax = fmaf(ex, w0.x, ax);
        ay = fmaf(ex, w0.y, ay);
        az = fmaf(ex, w1.x, az);
        aw = fmaf(ex, w1.y, aw);
    }
    const float invz = 1.0f / z;

    float4* h4 = (float4*)g_h;
    float4 b = ((const float4*)bg)[lane];
    float4 hin = h4[(size_t)d * 32 + lane];
    float4 o;
    o.x = fmaxf(fmaf(ax, invz, b.x), 0.f) + hin.x;
    o.y = fmaxf(fmaf(ay, invz, b.y), 0.f) + hin.y;
    o.z = fmaxf(fmaf(az, invz, b.z), 0.f) + hin.z;
    o.w = fmaxf(fmaf(aw, invz, b.w), 0.f) + hin.w;
    h4[(size_t)d * 32 + lane] = o;
    *(uint2*)&g_h16[(size_t)d * 128 + fo] =
        make_uint2(pack_f16(o.x, o.y), pack_f16(o.z, o.w));
}

// ---------------------------------------------------------------------------
// Fused pool + final projection; re-zeroes g_deg/g_total for the next run.
// ---------------------------------------------------------------------------
__global__ void k_poolfinal(const void* __restrict__ ei,
                            const void* __restrict__ batch,
                            const float* __restrict__ W2,
                            const float* __restrict__ b2,
                            float* __restrict__ out) {
    __shared__ float ps[128];
    __shared__ int s_lo, s_hi, s64;
    const int g = blockIdx.x;
    const int tid = threadIdx.x;
    probe_is64(ei, &s64);
    __syncthreads();
    if (tid == 0) {
        int lo = 0, hi = NN;
        while (lo < hi) { int mid = (lo + hi) >> 1; if (load_idx2(batch, mid, s64) < g) lo = mid + 1; else hi = mid; }
        s_lo = lo;
        lo = 0; hi = NN;
        int g1 = g + 1;
        while (lo < hi) { int mid = (lo + hi) >> 1; if (load_idx2(batch, mid, s64) < g1) lo = mid + 1; else hi = mid; }
        s_hi = lo;
    }
    __syncthreads();
    float acc = 0.f;
    for (int i = s_lo; i < s_hi; ++i) acc += g_h[(size_t)i * 128 + tid];
    ps[tid] = acc;
    __syncthreads();
    if (tid < 64) {
        float o = b2[tid];
        #pragma unroll 8
        for (int k = 0; k < 128; ++k)
            o = fmaf(ps[k], W2[k * 64 + tid], o);
        out[g * 64 + tid] = o;
    }
    // reset CSR counters for the next invocation
    for (int i = g * 128 + tid; i < NN; i += NG * 128) g_deg[i] = 0;
    if (g == 0 && tid == 0) g_total = 0;
}

// ---------------------------------------------------------------------------
// Launch: CSR branch forked onto a side stream (overlaps k_mma_x + first
// k_mma_h), joined before the first aggregation. Event fork/join is the
// supported pattern for parallel branches under stream capture.
// ---------------------------------------------------------------------------
extern "C" void kernel_launch(void* const* d_in, const int* in_sizes, int n_in,
                              void* d_out, int out_size) {
    const float* x     = (const float*)d_in[0];
    const void*  ei    = d_in[1];
    const void*  batch = d_in[2];
    const float* W1    = (const float*)d_in[3];
    const float* b1    = (const float*)d_in[4];
    const float* Wg    = (const float*)d_in[5];
    const float* asrc  = (const float*)d_in[6];
    const float* adst  = (const float*)d_in[7];
    const float* bg    = (const float*)d_in[8];
    const float* W2    = (const float*)d_in[9];
    const float* b2    = (const float*)d_in[10];
    float*       out   = (float*)d_out;

    const int gemm_blocks = (NN + 63) / 64;
    const int node_warp_blocks = (NN * 32 + 255) / 256;

    cudaStream_t s2 = 0;
    cudaEvent_t ev_root = 0, ev_csr = 0;
    bool forked =
        (cudaStreamCreateWithFlags(&s2, cudaStreamNonBlocking) == cudaSuccess) &&
        (cudaEventCreateWithFlags(&ev_root, cudaEventDisableTiming) == cudaSuccess) &&
        (cudaEventCreateWithFlags(&ev_csr, cudaEventDisableTiming) == cudaSuccess);

    if (forked) {
        // fork: CSR chain on s2, rooted at current head of stream 0
        cudaEventRecord(ev_root, 0);
        cudaStreamWaitEvent(s2, ev_root, 0);
        k_hist<<<(EE + 255) / 256, 256, 0, s2>>>(ei);
        k_alloc<<<(NN + 255) / 256, 256, 0, s2>>>();
        k_scatter<<<(EE + 255) / 256, 256, 0, s2>>>(ei);
        cudaEventRecord(ev_csr, s2);
    } else {
        // fallback: fully sequential on stream 0
        k_hist<<<(EE + 255) / 256, 256>>>(ei);
        k_alloc<<<(NN + 255) / 256, 256>>>();
        k_scatter<<<(EE + 255) / 256, 256>>>(ei);
    }

    // main chain on stream 0 (independent of CSR until first aggregation)
    k_mma_x<<<gemm_blocks, 256>>>(x, W1, b1);
    k_mma_h<<<gemm_blocks, 256>>>(Wg, asrc, adst);

    if (forked) cudaStreamWaitEvent(0, ev_csr, 0);   // join before aggregation

    k_gat_aggr<<<node_warp_blocks, 256>>>(bg);

    for (int l = 1; l < NLAYERS; ++l) {
        k_mma_h<<<gemm_blocks, 256>>>(Wg + (size_t)l * 128 * 128,
                                      asrc + l * 128, adst + l * 128);
        k_gat_aggr<<<node_warp_blocks, 256>>>(bg + l * 128);
    }

    k_poolfinal<<<NG, 128>>>(ei, batch, W2, b2, out);
    // streams/events intentionally not destroyed (capture-safe; few calls)
}